// round 14
// baseline (speedup 1.0000x reference)
#include <cuda_runtime.h>
#include <math.h>
#include <stdint.h>

// ---------------------------------------------------------------------------
// Model_25975962206896: 4-qubit VQC, B=524288.
// Z = s† (W† M W) s ⇒ 15-term trig polynomial in (f0, f1).
//   setup_kernel: 1 block / 192 threads, shuffle-propagated popcount bins,
//                 EARLY cudaTriggerProgrammaticLaunchCompletion so the eval
//                 grid spins up concurrently (PDL).
//   eval_kernel : ILP-2; coefficient-independent work (loads, MUFU trig,
//                 Chebyshev, power weights) BEFORE cudaGridDependency-
//                 Synchronize, coefficient-dependent work after.
// ---------------------------------------------------------------------------

__device__ float g_cA[15];
__device__ float g_cB[15];

__device__ __forceinline__ float2 cmulf(float2 a, float2 b) {
    return make_float2(a.x * b.x - a.y * b.y, a.x * b.y + a.y * b.x);
}
__device__ __forceinline__ float2 caddf(float2 a, float2 b) {
    return make_float2(a.x + b.x, a.y + b.y);
}

// ---------------------------------------------------------------------------
// Setup kernel: 1 block, 192 threads.
// ---------------------------------------------------------------------------
__global__ void setup_kernel(const float* __restrict__ wU,
                             const float* __restrict__ wR) {
#if __CUDA_ARCH__ >= 900
    // Release the dependent (eval) grid immediately; its coefficient reads
    // are ordered by cudaGridDependencySynchronize on the consumer side.
    cudaTriggerProgrammaticLaunchCompletion();
#endif

    __shared__ float2 gates[6][4][2][2];
    __shared__ float  isc[6], iss[6];
    __shared__ float2 sS[16][5];
    __shared__ float  sGx[15][4], sGy[15][4];

    const int tid = threadIdx.x;

    if (tid >= 160 && tid < 184) {
        int t = tid - 160;
        int l = t / 4, qb = t % 4;
        float a = wR[l * 12 + qb * 3 + 0];
        float b = wR[l * 12 + qb * 3 + 1];
        float c = wR[l * 12 + qb * 3 + 2];
        float sa, ca, sb, cb, sc3, cc3;
        __sincosf(0.5f * a, &sa, &ca);
        __sincosf(0.5f * b, &sb, &cb);
        __sincosf(0.5f * c, &sc3, &cc3);
        // g = RX(a) * RZ(b) * RX(c)
        float2 m1_00 = make_float2(ca, 0.f), m1_01 = make_float2(0.f, -sa);
        float2 m1_10 = make_float2(0.f, -sa), m1_11 = make_float2(ca, 0.f);
        float2 e0 = make_float2(cb, -sb), e1 = make_float2(cb, sb);
        float2 m3_00 = make_float2(cc3, 0.f), m3_01 = make_float2(0.f, -sc3);
        float2 m3_10 = make_float2(0.f, -sc3), m3_11 = make_float2(cc3, 0.f);
        float2 m23_00 = cmulf(e0, m3_00), m23_01 = cmulf(e0, m3_01);
        float2 m23_10 = cmulf(e1, m3_10), m23_11 = cmulf(e1, m3_11);
        gates[l][qb][0][0] = caddf(cmulf(m1_00, m23_00), cmulf(m1_01, m23_10));
        gates[l][qb][0][1] = caddf(cmulf(m1_00, m23_01), cmulf(m1_01, m23_11));
        gates[l][qb][1][0] = caddf(cmulf(m1_10, m23_00), cmulf(m1_11, m23_10));
        gates[l][qb][1][1] = caddf(cmulf(m1_10, m23_01), cmulf(m1_11, m23_11));
    } else if (tid >= 184 && tid < 190) {
        int l = tid - 184;
        float s, c;
        __sincosf(wU[l], &s, &c);
        isc[l] = c;
        iss[l] = s;
    }
    __syncthreads();

    if (tid < 160) {
        const int n = tid >> 5;
        const int lane = tid & 31;
        const int r = lane & 15;
        float2 z = make_float2((__popc(r) == n) ? 1.f : 0.f, 0.f);

        const int PAIRS[12] = {1, 2, 1, 3, 1, 2, 1, 3, 0, 3, 0, 2};
#pragma unroll
        for (int l = 0; l < 6; l++) {
            {
                int mp = 8 >> PAIRS[2 * l], mq = 8 >> PAIRS[2 * l + 1];
                float c = isc[l], s = iss[l];
                float ox = __shfl_xor_sync(0xFFFFFFFFu, z.x, mp | mq);
                float oy = __shfl_xor_sync(0xFFFFFFFFu, z.y, mp | mq);
                bool act = ((r & mp) != 0) != ((r & mq) != 0);
                if (act)
                    z = make_float2(fmaf(c, z.x, -s * oy), fmaf(c, z.y, s * ox));
            }
#pragma unroll
            for (int qb = 0; qb < 4; qb++) {
                int mask = 8 >> qb;
                float ox = __shfl_xor_sync(0xFFFFFFFFu, z.x, mask);
                float oy = __shfl_xor_sync(0xFFFFFFFFu, z.y, mask);
                bool hi = (r & mask) != 0;
                float2 ga = hi ? gates[l][qb][1][1] : gates[l][qb][0][0];
                float2 gb = hi ? gates[l][qb][1][0] : gates[l][qb][0][1];
                float2 nz;
                nz.x = ga.x * z.x - ga.y * z.y + gb.x * ox - gb.y * oy;
                nz.y = ga.x * z.y + ga.y * z.x + gb.x * oy + gb.y * ox;
                z = nz;
            }
        }
        if (lane < 16) sS[r][n] = z;
    }
    __syncthreads();

    // Parallel phase C: 60 threads compute 4-term partials per pair.
    const int NA[15] = {0, 0, 0, 0, 0, 1, 1, 1, 1, 2, 2, 2, 3, 3, 4};
    const int NB[15] = {0, 1, 2, 3, 4, 1, 2, 3, 4, 2, 3, 4, 3, 4, 4};
    if (tid < 60) {
        int k = tid >> 2, ch = tid & 3;
        int na = NA[k], nb = NB[k];
        float gx = 0.f, gy = 0.f;
#pragma unroll
        for (int j = 0; j < 4; j++) {
            int i = ch * 4 + j;
            float m = (i < 8) ? 1.f : -1.f;   // qubit 0 = bit 3
            float2 a = sS[i][na], b = sS[i][nb];
            gx += m * (a.x * b.x + a.y * b.y);
            gy += m * (a.x * b.y - a.y * b.x);
        }
        sGx[k][ch] = gx;
        sGy[k][ch] = gy;
    }
    __syncthreads();

    if (tid < 15) {
        float gx = (sGx[tid][0] + sGx[tid][1]) + (sGx[tid][2] + sGx[tid][3]);
        float gy = (sGy[tid][0] + sGy[tid][1]) + (sGy[tid][2] + sGy[tid][3]);
        if (NA[tid] == NB[tid]) { g_cA[tid] = gx;       g_cB[tid] = 0.f; }
        else                    { g_cA[tid] = 2.f * gx; g_cB[tid] = -2.f * gy; }
    }
}

// ---------------------------------------------------------------------------
// Eval kernel: 2 elements/thread, split around the grid dependency sync.
// ---------------------------------------------------------------------------
__global__ __launch_bounds__(128) void eval_kernel(
    const float4* __restrict__ in, const float* __restrict__ scp,
    const float* __restrict__ bip, float2* __restrict__ out) {

    int t = blockIdx.x * blockDim.x + threadIdx.x;
    float4 v = in[t];

    // ---- PRE-SYNC: everything independent of the coefficients ----
    // element 0: (f0,f1) = (v.x, v.y); element 1: (v.z, v.w)
    float sA_, cA_, s1A, c1A, sB_, cB_, s1B, c1B;
    __sincosf(0.5f * v.y, &sA_, &cA_);
    __sincosf(v.x, &s1A, &c1A);
    __sincosf(0.5f * v.w, &sB_, &cB_);
    __sincosf(v.z, &s1B, &c1B);

    // Chebyshev m=2..4, element 0
    float c2A = fmaf(2.0f * c1A, c1A, -1.0f);
    float s2A = 2.0f * s1A * c1A;
    float c3A = fmaf(c2A, c1A, -s2A * s1A);
    float s3A = fmaf(s2A, c1A, c2A * s1A);
    float c4A = fmaf(c3A, c1A, -s3A * s1A);
    float s4A = fmaf(s3A, c1A, c3A * s1A);
    // element 1
    float c2B = fmaf(2.0f * c1B, c1B, -1.0f);
    float s2B = 2.0f * s1B * c1B;
    float c3B = fmaf(c2B, c1B, -s2B * s1B);
    float s3B = fmaf(s2B, c1B, c2B * s1B);
    float c4B = fmaf(c3B, c1B, -s3B * s1B);
    float s4B = fmaf(s3B, c1B, c3B * s1B);

    // power weights w[p] = c^(8-p) s^p, element 0
    float ccA = cA_ * cA_, ssA = sA_ * sA_;
    float c4pA = ccA * ccA, s4pA = ssA * ssA;
    float c3pA = ccA * cA_, s3pA = ssA * sA_;
    float w0A = c4pA * c4pA;
    float w1A = (c4pA * c3pA) * sA_;
    float w2A = (c4pA * ccA) * ssA;
    float w3A = (c4pA * cA_) * s3pA;
    float w4A = c4pA * s4pA;
    float w5A = c3pA * (s4pA * sA_);
    float w6A = ccA * (s4pA * ssA);
    float w7A = cA_ * (s4pA * s3pA);
    float w8A = s4pA * s4pA;
    // element 1
    float ccB = cB_ * cB_, ssB = sB_ * sB_;
    float c4pB = ccB * ccB, s4pB = ssB * ssB;
    float c3pB = ccB * cB_, s3pB = ssB * sB_;
    float w0B = c4pB * c4pB;
    float w1B = (c4pB * c3pB) * sB_;
    float w2B = (c4pB * ccB) * ssB;
    float w3B = (c4pB * cB_) * s3pB;
    float w4B = c4pB * s4pB;
    float w5B = c3pB * (s4pB * sB_);
    float w6B = ccB * (s4pB * ssB);
    float w7B = cB_ * (s4pB * s3pB);
    float w8B = s4pB * s4pB;

#if __CUDA_ARCH__ >= 900
    cudaGridDependencySynchronize();
#endif

    // ---- POST-SYNC: coefficient-dependent work ----
    float A[15], B[15];
#pragma unroll
    for (int k = 0; k < 15; k++) {
        A[k] = __ldg(&g_cA[k]);
        B[k] = __ldg(&g_cB[k]);
    }
    const float scale = __ldg(scp);
    const float bias  = __ldg(bip);
    const float K = 0.011180339887f;  // sqrt(2/1000)/4

    // element 0
    float T1  = fmaf(A[1],  c1A, B[1]  * s1A);
    float T6  = fmaf(A[6],  c1A, B[6]  * s1A);
    float T10 = fmaf(A[10], c1A, B[10] * s1A);
    float T13 = fmaf(A[13], c1A, B[13] * s1A);
    float T2  = fmaf(A[2],  c2A, B[2]  * s2A);
    float T7  = fmaf(A[7],  c2A, B[7]  * s2A);
    float T11 = fmaf(A[11], c2A, B[11] * s2A);
    float T3  = fmaf(A[3],  c3A, B[3]  * s3A);
    float T8  = fmaf(A[8],  c3A, B[8]  * s3A);
    float T4  = fmaf(A[4],  c4A, B[4]  * s4A);
    float q0 = fmaf(w0A, A[0], w1A * T1);
    float q1 = fmaf(w2A, A[5] + T2, w3A * (T6 + T3));
    float q2 = fmaf(w4A, A[9] + T7 + T4, w5A * (T10 + T8));
    float q3 = fmaf(w6A, A[12] + T11, w7A * T13);
    float Z0 = (q0 + q1) + (q2 + q3) + w8A * A[14];

    // element 1
    float U1  = fmaf(A[1],  c1B, B[1]  * s1B);
    float U6  = fmaf(A[6],  c1B, B[6]  * s1B);
    float U10 = fmaf(A[10], c1B, B[10] * s1B);
    float U13 = fmaf(A[13], c1B, B[13] * s1B);
    float U2  = fmaf(A[2],  c2B, B[2]  * s2B);
    float U7  = fmaf(A[7],  c2B, B[7]  * s2B);
    float U11 = fmaf(A[11], c2B, B[11] * s2B);
    float U3  = fmaf(A[3],  c3B, B[3]  * s3B);
    float U8  = fmaf(A[8],  c3B, B[8]  * s3B);
    float U4  = fmaf(A[4],  c4B, B[4]  * s4B);
    float r0 = fmaf(w0B, A[0], w1B * U1);
    float r1 = fmaf(w2B, A[5] + U2, w3B * (U6 + U3));
    float r2 = fmaf(w4B, A[9] + U7 + U4, w5B * (U10 + U8));
    float r3 = fmaf(w6B, A[12] + U11, w7B * U13);
    float Z1 = (r0 + r1) + (r2 + r3) + w8B * A[14];

    float2 r;
    r.x = fmaf(scale, fmaf(K, fmaf(Z0, Z0, -1.0f), Z0), bias);
    r.y = fmaf(scale, fmaf(K, fmaf(Z1, Z1, -1.0f), Z1), bias);
    out[t] = r;
}

// ---------------------------------------------------------------------------
extern "C" void kernel_launch(void* const* d_in, const int* in_sizes, int n_in,
                              void* d_out, int out_size) {
    const float* inputs = (const float*)d_in[0];  // [B,2] float32
    const float* wU     = (const float*)d_in[1];  // [6]
    const float* wR     = (const float*)d_in[2];  // [6,4,3]
    const float* sc     = (const float*)d_in[3];  // [] out_scale
    const float* bi     = (const float*)d_in[4];  // [] out_bias

    setup_kernel<<<1, 192>>>(wU, wR);

    int nthreads = out_size / 2;  // 2 elements per thread
    int blocks = (nthreads + 127) / 128;

    // PDL launch: eval grid spins up while setup runs (setup triggers early);
    // cudaGridDependencySynchronize inside eval orders the coefficient reads.
    cudaLaunchConfig_t cfg = {};
    cfg.gridDim = dim3((unsigned)blocks);
    cfg.blockDim = dim3(128);
    cfg.dynamicSmemBytes = 0;
    cfg.stream = 0;
    cudaLaunchAttribute attr[1];
    attr[0].id = cudaLaunchAttributeProgrammaticStreamSerialization;
    attr[0].val.programmaticStreamSerializationAllowed = 1;
    cfg.attrs = attr;
    cfg.numAttrs = 1;
    cudaError_t err = cudaLaunchKernelEx(&cfg, eval_kernel,
                                         (const float4*)inputs, sc, bi,
                                         (float2*)d_out);
    if (err != cudaSuccess) {
        // Fallback: plain launch (correct, just serialized).
        eval_kernel<<<blocks, 128>>>((const float4*)inputs, sc, bi,
                                     (float2*)d_out);
    }
}